// round 17
// baseline (speedup 1.0000x reference)
#include <cuda_runtime.h>

#define S_GRID 14
#define N_EL   30
#define NBOX   16
#define IMG_FLOATS 5880              // 196*30
#define CONF_PER_IMG 392             // 196 rows * 2 conf channels
#define NTHREADS   256
#define NBLOCKS    1216              // 152 SMs * 8; 40-reg natural compile, 6 resident/SM

__device__ double       g_acc;
__device__ unsigned int g_count;

__device__ __forceinline__ float jac(float ax1, float ay1, float ax2, float ay2,
                                     float tx, float ty, float tz, float tw)
{
    float ltx = fmaxf(ax1, tx);
    float lty = fmaxf(ay1, ty);
    float rbx = fminf(ax2, tz);
    float rby = fminf(ay2, tw);
    float wi = fmaxf(rbx - ltx, 0.0f);
    float hi = fmaxf(rby - lty, 0.0f);
    float inter = wi * hi;
    float area_a = (ax2 - ax1) * (ay2 - ay1);
    float area_b = (tz - tx) * (tw - ty);
    float uni = area_a + area_b - inter;
    if (uni == 0.0f) uni = 1.0f;
    return inter / uni;
}

__global__ __launch_bounds__(NTHREADS)   // NO minBlocks cap: keeps natural 40 regs
void yolo_kernel(const float* __restrict__ pred,
                 const float* __restrict__ boxes,
                 const int*   __restrict__ classes,
                 float* __restrict__ out,
                 int batch)
{
    __shared__ double bsum;

    const int tid   = threadIdx.x;
    const int lane  = tid & 31;
    const int gwarp = (blockIdx.x * NTHREADS + tid) >> 5;

    if (tid == 0) bsum = 0.0;
    __syncthreads();                   // order bsum=0 before any warp's atomicAdd

    float facc = 0.0f;

    // ============ coord-correction phase (one warp per image) =================
    // 9728 warps >= 4096 images: at most one image per warp at this shape.
    for (int img = gwarp; img < batch; img += NBLOCKS * (NTHREADS / 32)) {
        int   ci = -1 - lane;              // unique dummies for lanes 16..31
        float dx = 0.f, dy = 0.f, bw = 0.f, bh = 0.f;
        int   cls = 0;
        if (lane < NBOX) {
            float4 bb = reinterpret_cast<const float4*>(boxes)[img * NBOX + lane];
            cls = classes[img * NBOX + lane];
            bw = bb.z - bb.x;
            bh = bb.w - bb.y;
            float cx = (bb.x + bb.z) * 0.5f;
            float cy = (bb.y + bb.w) * 0.5f;
            float vx = cx * 14.0f;
            float vy = cy * 14.0f;
            float ix = fminf(fmaxf(ceilf(vx) - 1.0f, 0.0f), 13.0f);
            float iy = fminf(fmaxf(ceilf(vy) - 1.0f, 0.0f), 13.0f);
            dx = vx - ix;
            dy = vy - iy;
            ci = (int)iy * S_GRID + (int)ix;
        }
        unsigned m = __match_any_sync(0xFFFFFFFFu, ci);
        // winner = highest lane in same-cell group = LAST writer (JAX scatter order);
        // its own (dx,dy,bw,bh,cls) ARE the cell's target values.
        if (lane < NBOX && (31 - __clz(m)) == lane) {
            const float2* r2 = reinterpret_cast<const float2*>(pred)
                             + (size_t)img * (IMG_FLOATS / 2) + ci * (N_EL / 2);
            float2 a0 = __ldg(r2 + 0), a1 = __ldg(r2 + 1), a2 = __ldg(r2 + 2),
                   a3 = __ldg(r2 + 3), a4 = __ldg(r2 + 4);
            // pred box0 = p[0..3], conf p[4]=a2.x ; box1 = p[5..8], conf p[9]=a4.y
            float iou0 = jac(a0.x, a0.y, a1.x, a1.y, dx, dy, bw, bh);
            float iou1 = jac(a2.y, a3.x, a3.y, a4.x, dx, dy, bw, bh);
            bool sel1 = iou1 > iou0;       // tie -> box0 (argmax first-max)
            float bx  = sel1 ? a2.y : a0.x;
            float by  = sel1 ? a3.x : a0.y;
            float bw_ = sel1 ? a3.y : a1.x;
            float bh_ = sel1 ? a4.x : a1.y;
            float bc  = sel1 ? a4.y : a2.x;

            // class loss over channels 10..29; one-hot at 9+cls => hot at cls-1
            float closs = 0.0f;
            #pragma unroll
            for (int i = 0; i < 10; i++) {
                float2 cc = __ldg(r2 + 5 + i);
                float ex = cc.x - ((cls == 2 * i + 1) ? 1.0f : 0.0f);
                float ey = cc.y - ((cls == 2 * i + 2) ? 1.0f : 0.0f);
                closs += ex * ex + ey * ey;
            }

            float dconf = bc - 1.0f;
            float d0 = bx - dx;
            float d1 = by - dy;
            float d2 = sqrtf(bw_) - sqrtf(bw);
            float d3 = sqrtf(bh_) - sqrtf(bh);
            // subtract this row's conf terms (stream phase adds them for ALL rows)
            facc += closs + dconf * dconf
                  + 5.0f * (d0 * d0 + d1 * d1 + d2 * d2 + d3 * d3)
                  - 0.5f * (a2.x * a2.x + a4.y * a4.y);
        }
    }

    // ============ streaming phase: ONLY the conf scalars ======================
    // Conf channels (==4,9 mod 30) repeat per 60-float period at float offsets
    // {4, 9, 34, 39}. q = conf id; fidx = 60*(q>>2) + FOFF[q&3].
    // Grid stride T % 4 == 0 keeps q&3 fixed per thread -> constant increment.
    // Flat predicated unroll-8: every thread issues ALL its loads back-to-back
    // (<=6 at this shape) -> MLP 5-6, no loop-carried tail.
    {
        const int total_q = batch * CONF_PER_IMG;    // 1,605,632
        const int T = NBLOCKS * NTHREADS;            // 311,296 (% 4 == 0)
        const int q0 = blockIdx.x * NTHREADS + tid;

        int r = q0 & 3;
        int foff = (r == 0) ? 4 : (r == 1) ? 9 : (r == 2) ? 34 : 39;
        const int fidx0 = 60 * (q0 >> 2) + foff;
        const int finc = 15 * T;                     // fidx step per q-step of T

        float s0 = 0.f, s1 = 0.f, s2 = 0.f, s3 = 0.f;
        #pragma unroll
        for (int i = 0; i < 8; i++) {
            if (q0 + i * T < total_q) {
                float c = __ldg(pred + fidx0 + i * finc);
                if ((i & 3) == 0) s0 = fmaf(c, c, s0);
                else if ((i & 3) == 1) s1 = fmaf(c, c, s1);
                else if ((i & 3) == 2) s2 = fmaf(c, c, s2);
                else s3 = fmaf(c, c, s3);
            }
        }
        // generality guard (dead at batch=4096: ceil(total_q/T) = 6 <= 8)
        int q = q0 + 8 * T;
        int fidx = fidx0 + 8 * finc;
        while (q < total_q) {
            float c = __ldg(pred + fidx);
            s0 = fmaf(c, c, s0);
            q += T;
            fidx += finc;
        }
        facc += 0.5f * ((s0 + s1) + (s2 + s3));
    }

    // ============ reduce ======================================================
    #pragma unroll
    for (int o = 16; o; o >>= 1)
        facc += __shfl_xor_sync(0xFFFFFFFFu, facc, o);
    if (lane == 0) atomicAdd(&bsum, (double)facc);
    __syncthreads();

    if (tid == 0) {
        atomicAdd(&g_acc, bsum);
        __threadfence();
        unsigned done = atomicAdd(&g_count, 1u);
        if (done == (unsigned)(NBLOCKS - 1)) {
            double total = atomicAdd(&g_acc, 0.0);   // coherent read of final sum
            out[0] = (float)total;
            g_acc = 0.0;          // reset for next graph replay
            g_count = 0u;
        }
    }
}

extern "C" void kernel_launch(void* const* d_in, const int* in_sizes, int n_in,
                              void* d_out, int out_size)
{
    const float* pred    = (const float*)d_in[0];   // [batch, 5880]
    const float* boxes   = (const float*)d_in[1];   // [batch, 16, 4]
    const int*   classes = (const int*)d_in[2];     // [batch, 16]
    float* out = (float*)d_out;

    int batch = in_sizes[0] / IMG_FLOATS;

    yolo_kernel<<<NBLOCKS, NTHREADS>>>(pred, boxes, classes, out, batch);
}